// round 1
// baseline (speedup 1.0000x reference)
#include <cuda_runtime.h>
#include <cuda_bf16.h>
#include <math.h>

#define H1 256
#define W1 256
#define HW1 65536
#define EPSF 1e-5f

// ---------------- scratch (device globals; no allocation allowed) ----------------
__device__ float g_h[2 * 64 * HW1];        // conv1 output (B,64,256,256)
__device__ float g_off[2 * 20 * HW1];      // off conv raw: ch 0-9 = offx, 10-19 = offy
__device__ float g_cumA[2 * 5 * HW1];      // morph0 cumulative y-offsets
__device__ float g_cumB[2 * 5 * HW1];      // morph1 cumulative x-offsets
__device__ float g_outraw[2 * 16 * HW1];   // raw dsconv outputs: ch0-7 morph0, ch8-15 morph1
__device__ float g_osum[20], g_osq[20];    // off GN stats (b*10 + group)
__device__ float g_ssum[8],  g_ssq[8];     // out GN stats (b*4 + group)

// ---------------- zero stats ----------------
__global__ void zero_stats_kernel() {
    int i = threadIdx.x;
    if (i < 20) { g_osum[i] = 0.f; g_osq[i] = 0.f; }
    if (i < 8)  { g_ssum[i] = 0.f; g_ssq[i] = 0.f; }
}

// ---------------- conv1 3x3 s2 pad1 (3->64) + BN + ReLU ----------------
__global__ void conv1_kernel(const float* __restrict__ x, const float* __restrict__ w,
                             const float* __restrict__ g, const float* __restrict__ bb,
                             const float* __restrict__ m, const float* __restrict__ v) {
    __shared__ float sw[64 * 27];
    __shared__ float sscale[64], sshift[64];
    int tid = threadIdx.x;
    for (int i = tid; i < 64 * 27; i += 256) sw[i] = w[i];
    if (tid < 64) {
        float sc = g[tid] * rsqrtf(v[tid] + EPSF);
        sscale[tid] = sc;
        sshift[tid] = bb[tid] - m[tid] * sc;
    }
    __syncthreads();

    int idx = blockIdx.x * 256 + tid;         // over B*H*W
    int b = idx / HW1, p = idx % HW1;
    int oy = p / W1, ox = p % W1;

    float patch[27];
    const float* xb = x + (size_t)b * 3 * 512 * 512;
    #pragma unroll
    for (int ic = 0; ic < 3; ic++)
        #pragma unroll
        for (int dy = 0; dy < 3; dy++) {
            int iy = 2 * oy - 1 + dy;
            #pragma unroll
            for (int dx = 0; dx < 3; dx++) {
                int ix = 2 * ox - 1 + dx;
                float val = 0.f;
                if (iy >= 0 && iy < 512 && ix >= 0 && ix < 512)
                    val = xb[(ic * 512 + iy) * 512 + ix];
                patch[ic * 9 + dy * 3 + dx] = val;
            }
        }

    float* hb = g_h + (size_t)b * 64 * HW1 + p;
    #pragma unroll 4
    for (int oc = 0; oc < 64; oc++) {
        float acc = 0.f;
        #pragma unroll
        for (int t = 0; t < 27; t++) acc = fmaf(patch[t], sw[oc * 27 + t], acc);
        acc = fmaf(acc, sscale[oc], sshift[oc]);
        hb[(size_t)oc * HW1] = fmaxf(acc, 0.f);
    }
}

// ---------------- both offset convs 3x3 pad1 (64 -> 10+10), tiled ----------------
__global__ void offconv_kernel(const float* __restrict__ wx, const float* __restrict__ bx,
                               const float* __restrict__ wy, const float* __restrict__ by) {
    __shared__ float tile[18][19];
    __shared__ float swt[20 * 9];
    int tx = threadIdx.x, ty = threadIdx.y;
    int tid = ty * 16 + tx;
    int b = blockIdx.z;
    int ox0 = blockIdx.x * 16, oy0 = blockIdx.y * 16;

    float acc[20];
    #pragma unroll
    for (int i = 0; i < 20; i++) acc[i] = (i < 10) ? bx[i] : by[i - 10];

    for (int c = 0; c < 64; c++) {
        const float* hp = g_h + ((size_t)b * 64 + c) * HW1;
        for (int i = tid; i < 18 * 18; i += 256) {
            int r = i / 18, col = i % 18;
            int iy = oy0 - 1 + r, ix = ox0 - 1 + col;
            float val = 0.f;
            if (iy >= 0 && iy < H1 && ix >= 0 && ix < W1) val = hp[iy * W1 + ix];
            tile[r][col] = val;
        }
        if (tid < 90) {
            swt[tid] = wx[(tid / 9) * 576 + c * 9 + (tid % 9)];
        } else if (tid < 180) {
            int t = tid - 90;
            swt[90 + t] = wy[(t / 9) * 576 + c * 9 + (t % 9)];
        }
        __syncthreads();

        float p9[9];
        #pragma unroll
        for (int dy = 0; dy < 3; dy++)
            #pragma unroll
            for (int dx = 0; dx < 3; dx++) p9[dy * 3 + dx] = tile[ty + dy][tx + dx];

        #pragma unroll
        for (int ch = 0; ch < 20; ch++) {
            #pragma unroll
            for (int t = 0; t < 9; t++) acc[ch] = fmaf(p9[t], swt[ch * 9 + t], acc[ch]);
        }
        __syncthreads();
    }

    int oy = oy0 + ty, ox = ox0 + tx;
    float* op = g_off + (size_t)b * 20 * HW1 + oy * W1 + ox;
    #pragma unroll
    for (int ch = 0; ch < 20; ch++) op[(size_t)ch * HW1] = acc[ch];
}

// ---------------- group stats (mode 0: off conv; mode 1: dsconv out) ----------------
__global__ void stats_kernel(int mode) {
    int gi = blockIdx.x;
    const float* base;
    float *sp, *qp;
    int n;
    if (mode == 0) {
        int b = gi / 10, grp = gi % 10;
        base = g_off + ((size_t)b * 20 + 2 * grp) * HW1;
        n = 2 * HW1;
        sp = &g_osum[gi]; qp = &g_osq[gi];
    } else {
        int b = gi / 4, grp = gi % 4;
        base = g_outraw + ((size_t)b * 16 + 4 * grp) * HW1;
        n = 4 * HW1;
        sp = &g_ssum[gi]; qp = &g_ssq[gi];
    }
    int per = n / gridDim.y;
    int start = blockIdx.y * per;
    float s = 0.f, q = 0.f;
    for (int i = start + threadIdx.x; i < start + per; i += blockDim.x) {
        float val = base[i];
        s += val;
        q = fmaf(val, val, q);
    }
    #pragma unroll
    for (int o = 16; o > 0; o >>= 1) {
        s += __shfl_down_sync(0xffffffffu, s, o);
        q += __shfl_down_sync(0xffffffffu, q, o);
    }
    __shared__ float ws[8], wq[8];
    int lane = threadIdx.x & 31, wid = threadIdx.x >> 5;
    if (lane == 0) { ws[wid] = s; wq[wid] = q; }
    __syncthreads();
    if (threadIdx.x == 0) {
        float S = 0.f, Q = 0.f;
        #pragma unroll
        for (int i = 0; i < 8; i++) { S += ws[i]; Q += wq[i]; }
        atomicAdd(sp, S);
        atomicAdd(qp, Q);
    }
}

// ---------------- GN + tanh + cumulative-offset ----------------
__global__ void cum_kernel(const float* __restrict__ gxg, const float* __restrict__ gxb,
                           const float* __restrict__ gyg, const float* __restrict__ gyb) {
    int idx = blockIdx.x * 256 + threadIdx.x;   // over B*H*W
    int b = idx / HW1, p = idx % HW1;

    float t[5];
    // morph 0: y_off = offx channels 0..4
    #pragma unroll
    for (int c = 0; c < 5; c++) {
        int gi = b * 10 + c / 2;
        float mean = g_osum[gi] * (1.f / 131072.f);
        float var  = g_osq[gi]  * (1.f / 131072.f) - mean * mean;
        float val = g_off[((size_t)b * 20 + c) * HW1 + p];
        t[c] = tanhf((val - mean) * rsqrtf(var + EPSF) * gxg[c] + gxb[c]);
    }
    {
        float* ca = g_cumA + (size_t)b * 5 * HW1 + p;
        ca[0 * HW1] = t[0] + t[1];
        ca[1 * HW1] = t[1];
        ca[2 * HW1] = 0.f;
        ca[3 * HW1] = t[3];
        ca[4 * HW1] = t[3] + t[4];
    }
    // morph 1: x_off = offy channels 5..9 (global off channels 15..19)
    #pragma unroll
    for (int c = 5; c < 10; c++) {
        int gi = b * 10 + 5 + c / 2;
        float mean = g_osum[gi] * (1.f / 131072.f);
        float var  = g_osq[gi]  * (1.f / 131072.f) - mean * mean;
        float val = g_off[((size_t)b * 20 + 10 + c) * HW1 + p];
        t[c - 5] = tanhf((val - mean) * rsqrtf(var + EPSF) * gyg[c] + gyb[c]);
    }
    {
        float* cb = g_cumB + (size_t)b * 5 * HW1 + p;
        cb[0 * HW1] = t[0] + t[1];
        cb[1 * HW1] = t[1];
        cb[2 * HW1] = 0.f;
        cb[3 * HW1] = t[3];
        cb[4 * HW1] = t[3] + t[4];
    }
}

// ---------------- fused bilinear-sample + K-strided conv (64 -> 8) ----------------
__global__ void sample_dsc_kernel(const float* __restrict__ dw, const float* __restrict__ db,
                                  int morph) {
    __shared__ float sw[2560];   // [oc][c][k] : oc*320 + c*5 + k
    int tid = threadIdx.x;
    for (int i = tid; i < 2560; i += 256) sw[i] = dw[i];
    __syncthreads();

    int idx = blockIdx.x * 256 + tid;
    int b = idx / HW1, p = idx % HW1;
    int hh = p / W1, ww = p % W1;

    float acc[8];
    #pragma unroll
    for (int oc = 0; oc < 8; oc++) acc[oc] = db[oc];

    const float* cum = (morph == 0 ? g_cumA : g_cumB) + (size_t)b * 5 * HW1 + p;
    int o0[5], o1[5];
    float wt[5];
    #pragma unroll
    for (int k = 0; k < 5; k++) {
        float off = cum[(size_t)k * HW1];
        if (morph == 0) {
            float y = fminf(fmaxf((float)hh + off, 0.f), 255.f);
            float y0 = floorf(y);
            wt[k] = y - y0;
            int i0 = (int)y0;
            int i1 = min(i0 + 1, 255);
            int xi = min(max(ww + k - 2, 0), 255);
            o0[k] = i0 * W1 + xi;
            o1[k] = i1 * W1 + xi;
        } else {
            float xx = fminf(fmaxf((float)ww + off, 0.f), 255.f);
            float x0 = floorf(xx);
            wt[k] = xx - x0;
            int i0 = (int)x0;
            int i1 = min(i0 + 1, 255);
            int yi = min(max(hh + k - 2, 0), 255);
            o0[k] = yi * W1 + i0;
            o1[k] = yi * W1 + i1;
        }
    }

    const float* hb = g_h + (size_t)b * 64 * HW1;
    for (int c = 0; c < 64; c++) {
        const float* hp = hb + (size_t)c * HW1;
        #pragma unroll
        for (int k = 0; k < 5; k++) {
            float a = hp[o0[k]];
            float bvl = hp[o1[k]];
            float val = fmaf(wt[k], bvl - a, a);   // (1-w)a + w b
            #pragma unroll
            for (int oc = 0; oc < 8; oc++)
                acc[oc] = fmaf(val, sw[oc * 320 + c * 5 + k], acc[oc]);
        }
    }

    float* op = g_outraw + ((size_t)b * 16 + morph * 8) * HW1 + p;
    #pragma unroll
    for (int oc = 0; oc < 8; oc++) op[(size_t)oc * HW1] = acc[oc];
}

// ---------------- GN+ReLU (both branches) + concat + 1x1 conv (16->64) + BN + ReLU ----------------
__global__ void final_kernel(const float* __restrict__ gx_g, const float* __restrict__ gx_b,
                             const float* __restrict__ gy_g, const float* __restrict__ gy_b,
                             const float* __restrict__ w2,
                             const float* __restrict__ bn2g, const float* __restrict__ bn2b,
                             const float* __restrict__ bn2m, const float* __restrict__ bn2v,
                             float* __restrict__ out) {
    __shared__ float sw[1024];
    __shared__ float sscale[64], sshift[64];
    int tid = threadIdx.x;
    for (int i = tid; i < 1024; i += 256) sw[i] = w2[i];
    if (tid < 64) {
        float sc = bn2g[tid] * rsqrtf(bn2v[tid] + EPSF);
        sscale[tid] = sc;
        sshift[tid] = bn2b[tid] - bn2m[tid] * sc;
    }
    __syncthreads();

    int idx = blockIdx.x * 256 + tid;
    int b = idx / HW1, p = idx % HW1;

    float cat[16];
    #pragma unroll
    for (int ch = 0; ch < 16; ch++) {
        int gi = b * 4 + ch / 4;
        float mean = g_ssum[gi] * (1.f / 262144.f);
        float var  = g_ssq[gi]  * (1.f / 262144.f) - mean * mean;
        float gamma = (ch < 8) ? gx_g[ch] : gy_g[ch - 8];
        float beta  = (ch < 8) ? gx_b[ch] : gy_b[ch - 8];
        float val = g_outraw[((size_t)b * 16 + ch) * HW1 + p];
        val = (val - mean) * rsqrtf(var + EPSF) * gamma + beta;
        cat[ch] = fmaxf(val, 0.f);
    }

    float* ob = out + (size_t)b * 64 * HW1 + p;
    #pragma unroll 4
    for (int oc = 0; oc < 64; oc++) {
        float s = 0.f;
        #pragma unroll
        for (int ch = 0; ch < 16; ch++) s = fmaf(cat[ch], sw[oc * 16 + ch], s);
        ob[(size_t)oc * HW1] = fmaxf(fmaf(s, sscale[oc], sshift[oc]), 0.f);
    }
}

// ---------------- launch ----------------
extern "C" void kernel_launch(void* const* d_in, const int* in_sizes, int n_in,
                              void* d_out, int out_size) {
    const float* x        = (const float*)d_in[0];
    const float* conv1_w  = (const float*)d_in[1];
    const float* bn1_g    = (const float*)d_in[2];
    const float* bn1_b    = (const float*)d_in[3];
    const float* bn1_m    = (const float*)d_in[4];
    const float* bn1_v    = (const float*)d_in[5];
    const float* offx_w   = (const float*)d_in[6];
    const float* offx_b   = (const float*)d_in[7];
    const float* gnoffx_g = (const float*)d_in[8];
    const float* gnoffx_b = (const float*)d_in[9];
    const float* dscx_w   = (const float*)d_in[10];
    const float* dscx_b   = (const float*)d_in[11];
    const float* gnx_g    = (const float*)d_in[12];
    const float* gnx_b    = (const float*)d_in[13];
    const float* offy_w   = (const float*)d_in[14];
    const float* offy_b   = (const float*)d_in[15];
    const float* gnoffy_g = (const float*)d_in[16];
    const float* gnoffy_b = (const float*)d_in[17];
    const float* dscy_w   = (const float*)d_in[18];
    const float* dscy_b   = (const float*)d_in[19];
    const float* gny_g    = (const float*)d_in[20];
    const float* gny_b    = (const float*)d_in[21];
    const float* conv2_w  = (const float*)d_in[22];
    const float* bn2_g    = (const float*)d_in[23];
    const float* bn2_b    = (const float*)d_in[24];
    const float* bn2_m    = (const float*)d_in[25];
    const float* bn2_v    = (const float*)d_in[26];
    float* out = (float*)d_out;

    zero_stats_kernel<<<1, 64>>>();
    conv1_kernel<<<512, 256>>>(x, conv1_w, bn1_g, bn1_b, bn1_m, bn1_v);
    offconv_kernel<<<dim3(16, 16, 2), dim3(16, 16)>>>(offx_w, offx_b, offy_w, offy_b);
    stats_kernel<<<dim3(20, 16), 256>>>(0);
    cum_kernel<<<512, 256>>>(gnoffx_g, gnoffx_b, gnoffy_g, gnoffy_b);
    sample_dsc_kernel<<<512, 256>>>(dscx_w, dscx_b, 0);
    sample_dsc_kernel<<<512, 256>>>(dscy_w, dscy_b, 1);
    stats_kernel<<<dim3(8, 32), 256>>>(1);
    final_kernel<<<512, 256>>>(gnx_g, gnx_b, gny_g, gny_b, conv2_w,
                               bn2_g, bn2_b, bn2_m, bn2_v, out);
}

// round 2
// speedup vs baseline: 1.3589x; 1.3589x over previous
#include <cuda_runtime.h>
#include <math.h>

#define H1 256
#define W1 256
#define HW1 65536
#define EPSF 1e-5f

typedef unsigned long long ull;

__device__ __forceinline__ ull pk2(float a, float b) {
    ull r; asm("mov.b64 %0,{%1,%2};" : "=l"(r) : "f"(a), "f"(b)); return r;
}
__device__ __forceinline__ ull dup2(float a) {
    ull r; asm("mov.b64 %0,{%1,%1};" : "=l"(r) : "f"(a)); return r;
}
__device__ __forceinline__ void fma2(ull& d, ull a, ull b) {
    asm("fma.rn.f32x2 %0,%1,%2,%0;" : "+l"(d) : "l"(a), "l"(b));
}
__device__ __forceinline__ float2 up2(ull u) {
    float2 r; asm("mov.b64 {%0,%1},%2;" : "=f"(r.x), "=f"(r.y) : "l"(u)); return r;
}

// ---------------- scratch ----------------
__device__ float g_h[2 * 64 * HW1];        // conv1 output
__device__ float g_off[2 * 8 * HW1];       // only the 8 offset channels actually sampled
__device__ float g_outraw[2 * 16 * HW1];   // dsconv raw outputs
__device__ float g_osum[20], g_osq[20];    // off GN stats
__device__ float g_ssum[8],  g_ssq[8];     // out GN stats

__global__ void zero_stats_kernel() {
    int i = threadIdx.x;
    if (i < 20) { g_osum[i] = 0.f; g_osq[i] = 0.f; }
    if (i < 8)  { g_ssum[i] = 0.f; g_ssq[i] = 0.f; }
}

// ---------------- conv1 3x3 s2 pad1 (3->64) + BN + ReLU, oc-pair packed ----------------
__global__ void __launch_bounds__(256) conv1_kernel(
        const float* __restrict__ x, const float* __restrict__ w,
        const float* __restrict__ g, const float* __restrict__ bb,
        const float* __restrict__ m, const float* __restrict__ v) {
    __shared__ ull swp[864];             // [t*32 + ocpair]
    __shared__ float ssc[64], ssh[64];
    int tid = threadIdx.x;
    for (int i = tid; i < 864; i += 256) {
        int t = i >> 5, op = i & 31;
        swp[i] = pk2(w[(2 * op) * 27 + t], w[(2 * op + 1) * 27 + t]);
    }
    if (tid < 64) {
        float sc = g[tid] * rsqrtf(v[tid] + EPSF);
        ssc[tid] = sc; ssh[tid] = bb[tid] - m[tid] * sc;
    }
    __syncthreads();

    int idx = blockIdx.x * 256 + tid;
    int b = idx >> 16, p = idx & 65535;
    int oy = p >> 8, ox = p & 255;
    const float* xb = x + (size_t)b * 3 * 512 * 512;

    ull pd[27];
    #pragma unroll
    for (int ic = 0; ic < 3; ic++)
        #pragma unroll
        for (int dy = 0; dy < 3; dy++) {
            int iy = 2 * oy - 1 + dy;
            #pragma unroll
            for (int dx = 0; dx < 3; dx++) {
                int ix = 2 * ox - 1 + dx;
                float val = 0.f;
                if (iy >= 0 && ix >= 0) val = xb[(ic * 512 + iy) * 512 + ix];
                pd[ic * 9 + dy * 3 + dx] = dup2(val);
            }
        }

    float* hb = g_h + (size_t)b * 64 * HW1 + p;
    #pragma unroll 1
    for (int half = 0; half < 2; half++) {
        ull acc[16];
        #pragma unroll
        for (int j = 0; j < 16; j++) acc[j] = 0ull;
        #pragma unroll
        for (int t = 0; t < 27; t++)
            #pragma unroll
            for (int j = 0; j < 16; j++)
                fma2(acc[j], pd[t], swp[t * 32 + half * 16 + j]);
        #pragma unroll
        for (int j = 0; j < 16; j++) {
            int oc = (half * 16 + j) * 2;
            float2 vv = up2(acc[j]);
            hb[(size_t)oc * HW1]       = fmaxf(fmaf(vv.x, ssc[oc],     ssh[oc]),     0.f);
            hb[(size_t)(oc + 1) * HW1] = fmaxf(fmaf(vv.y, ssc[oc + 1], ssh[oc + 1]), 0.f);
        }
    }
}

// ---------------- offset convs 3x3 pad1 (64 -> 20), 2px/thread packed, fused stats ----------------
__global__ void __launch_bounds__(256) offconv_kernel(
        const float* __restrict__ wx, const float* __restrict__ bx,
        const float* __restrict__ wy, const float* __restrict__ by) {
    __shared__ float tile[34 * 19];
    __shared__ ull swc[180];             // duplicated weights for current input channel
    int tx = threadIdx.x, ty = threadIdx.y;
    int tid = ty * 16 + tx;
    int b = blockIdx.z;
    int ox0 = blockIdx.x * 16, oy0 = blockIdx.y * 32;

    ull acc[20];
    #pragma unroll
    for (int ch = 0; ch < 20; ch++)
        acc[ch] = dup2(ch < 10 ? bx[ch] : by[ch - 10]);

    for (int c = 0; c < 64; c++) {
        __syncthreads();
        const float* hp = g_h + ((size_t)b * 64 + c) * HW1;
        for (int i = tid; i < 34 * 18; i += 256) {
            int r = i / 18, col = i - r * 18;
            int iy = oy0 - 1 + r, ix = ox0 - 1 + col;
            float val = 0.f;
            if (iy >= 0 && iy < H1 && ix >= 0 && ix < W1) val = hp[iy * W1 + ix];
            tile[r * 19 + col] = val;
        }
        if (tid < 180) {
            int ch = tid / 9;
            float wv = (ch < 10) ? wx[ch * 576 + c * 9 + (tid - ch * 9)]
                                 : wy[(ch - 10) * 576 + c * 9 + (tid - ch * 9)];
            swc[tid] = dup2(wv);
        }
        __syncthreads();

        ull pk[9];
        #pragma unroll
        for (int dy = 0; dy < 3; dy++)
            #pragma unroll
            for (int dx = 0; dx < 3; dx++)
                pk[dy * 3 + dx] = pk2(tile[(ty + dy) * 19 + tx + dx],
                                      tile[(ty + 16 + dy) * 19 + tx + dx]);
        #pragma unroll
        for (int ch = 0; ch < 20; ch++)
            #pragma unroll
            for (int t = 0; t < 9; t++)
                fma2(acc[ch], pk[t], swc[ch * 9 + t]);
    }

    // store only the channels the sample kernel needs
    int p0 = (oy0 + ty) * W1 + ox0 + tx;
    int p1 = p0 + 16 * W1;
    const int chs[8] = {0, 1, 3, 4, 15, 16, 18, 19};
    float* ob = g_off + (size_t)b * 8 * HW1;
    #pragma unroll
    for (int s = 0; s < 8; s++) {
        float2 vv = up2(acc[chs[s]]);
        ob[(size_t)s * HW1 + p0] = vv.x;
        ob[(size_t)s * HW1 + p1] = vv.y;
    }

    // fused GN statistics (10 groups of 2 channels)
    __syncthreads();
    float* red = tile;
    int lane = tid & 31, wid = tid >> 5;
    for (int gi = 0; gi < 10; gi++) {
        float2 a = up2(acc[2 * gi]), c2 = up2(acc[2 * gi + 1]);
        float s = a.x + a.y + c2.x + c2.y;
        float q = a.x * a.x + a.y * a.y + c2.x * c2.x + c2.y * c2.y;
        #pragma unroll
        for (int o = 16; o > 0; o >>= 1) {
            s += __shfl_down_sync(0xffffffffu, s, o);
            q += __shfl_down_sync(0xffffffffu, q, o);
        }
        if (lane == 0) { red[wid] = s; red[8 + wid] = q; }
        __syncthreads();
        if (tid == 0) {
            float S = 0.f, Q = 0.f;
            #pragma unroll
            for (int i = 0; i < 8; i++) { S += red[i]; Q += red[8 + i]; }
            atomicAdd(&g_osum[b * 10 + gi], S);
            atomicAdd(&g_osq[b * 10 + gi], Q);
        }
        __syncthreads();
    }
}

// ---------------- fused GN+tanh+cum + bilinear sample + K-conv (64->8) + stats ----------------
__global__ void __launch_bounds__(256) sample_kernel(
        const float* __restrict__ dwx, const float* __restrict__ dbx,
        const float* __restrict__ dwy, const float* __restrict__ dby,
        const float* __restrict__ gxg, const float* __restrict__ gxb,
        const float* __restrict__ gyg, const float* __restrict__ gyb) {
    int morph = blockIdx.y;
    const float* dw = morph ? dwy : dwx;
    const float* db = morph ? dby : dbx;

    __shared__ float sw4[2560];          // [(c*5+k)*8 + oc]
    __shared__ float sA[4], sB[4];
    __shared__ float red[32];
    int tid = threadIdx.x;
    int idx = blockIdx.x * 256 + tid;
    int b = idx >> 16, p = idx & 65535;

    for (int i = tid; i < 2560; i += 256) sw4[i] = dw[(i & 7) * 320 + (i >> 3)];
    if (tid < 4) {
        int gi, ci; float gamma, beta;
        if (morph == 0) {
            const int gtab[4] = {0, 0, 1, 2}; const int ctab[4] = {0, 1, 3, 4};
            gi = b * 10 + gtab[tid]; ci = ctab[tid];
            gamma = gxg[ci]; beta = gxb[ci];
        } else {
            const int gtab[4] = {7, 8, 9, 9}; const int ctab[4] = {5, 6, 8, 9};
            gi = b * 10 + gtab[tid]; ci = ctab[tid];
            gamma = gyg[ci]; beta = gyb[ci];
        }
        float mean = g_osum[gi] * (1.f / 131072.f);
        float var  = g_osq[gi]  * (1.f / 131072.f) - mean * mean;
        float rs = rsqrtf(var + EPSF) * gamma;
        sA[tid] = rs; sB[tid] = beta - mean * rs;
    }
    __syncthreads();

    int hh = p >> 8, ww = p & 255;
    const float* ob = g_off + ((size_t)b * 8 + morph * 4) * HW1 + p;
    float t0 = tanhf(fmaf(ob[0 * (size_t)HW1], sA[0], sB[0]));
    float t1 = tanhf(fmaf(ob[1 * (size_t)HW1], sA[1], sB[1]));
    float t2 = tanhf(fmaf(ob[2 * (size_t)HW1], sA[2], sB[2]));
    float t3 = tanhf(fmaf(ob[3 * (size_t)HW1], sA[3], sB[3]));
    float cum[5] = {t0 + t1, t1, 0.f, t2, t2 + t3};

    int o0[5], o1[5]; float wt[5];
    #pragma unroll
    for (int k = 0; k < 5; k++) {
        if (morph == 0) {
            float y = fminf(fmaxf((float)hh + cum[k], 0.f), 255.f);
            float y0 = floorf(y);
            wt[k] = y - y0;
            int i0 = (int)y0;
            int i1 = min(i0 + 1, 255);
            int xi = min(max(ww + k - 2, 0), 255);
            o0[k] = i0 * W1 + xi; o1[k] = i1 * W1 + xi;
        } else {
            float xx = fminf(fmaxf((float)ww + cum[k], 0.f), 255.f);
            float x0 = floorf(xx);
            wt[k] = xx - x0;
            int i0 = (int)x0;
            int i1 = min(i0 + 1, 255);
            int yi = min(max(hh + k - 2, 0), 255);
            o0[k] = yi * W1 + i0; o1[k] = yi * W1 + i1;
        }
    }

    float4 d0 = *(const float4*)db;
    float4 d1 = *(const float4*)(db + 4);
    ull a01 = pk2(d0.x, d0.y), a23 = pk2(d0.z, d0.w);
    ull a45 = pk2(d1.x, d1.y), a67 = pk2(d1.z, d1.w);

    const float* hb = g_h + (size_t)b * 64 * HW1;
    const ulonglong2* swu = (const ulonglong2*)sw4;
    for (int c = 0; c < 64; c++) {
        const float* hp = hb + (size_t)c * HW1;
        #pragma unroll
        for (int k = 0; k < 5; k++) {
            float va = hp[o0[k]], vb = hp[o1[k]];
            ull v2 = dup2(fmaf(wt[k], vb - va, va));
            ulonglong2 wA = swu[(c * 5 + k) * 2];
            ulonglong2 wB = swu[(c * 5 + k) * 2 + 1];
            fma2(a01, v2, wA.x); fma2(a23, v2, wA.y);
            fma2(a45, v2, wB.x); fma2(a67, v2, wB.y);
        }
    }

    float2 r01 = up2(a01), r23 = up2(a23), r45 = up2(a45), r67 = up2(a67);
    float* op = g_outraw + ((size_t)b * 16 + morph * 8) * HW1 + p;
    op[0 * (size_t)HW1] = r01.x; op[1 * (size_t)HW1] = r01.y;
    op[2 * (size_t)HW1] = r23.x; op[3 * (size_t)HW1] = r23.y;
    op[4 * (size_t)HW1] = r45.x; op[5 * (size_t)HW1] = r45.y;
    op[6 * (size_t)HW1] = r67.x; op[7 * (size_t)HW1] = r67.y;

    // fused out-GN stats: group0 = oc0-3, group1 = oc4-7
    float s0 = r01.x + r01.y + r23.x + r23.y;
    float q0 = r01.x * r01.x + r01.y * r01.y + r23.x * r23.x + r23.y * r23.y;
    float s1 = r45.x + r45.y + r67.x + r67.y;
    float q1 = r45.x * r45.x + r45.y * r45.y + r67.x * r67.x + r67.y * r67.y;
    #pragma unroll
    for (int o = 16; o > 0; o >>= 1) {
        s0 += __shfl_down_sync(0xffffffffu, s0, o);
        q0 += __shfl_down_sync(0xffffffffu, q0, o);
        s1 += __shfl_down_sync(0xffffffffu, s1, o);
        q1 += __shfl_down_sync(0xffffffffu, q1, o);
    }
    int lane = tid & 31, wid = tid >> 5;
    if (lane == 0) { red[wid] = s0; red[8 + wid] = q0; red[16 + wid] = s1; red[24 + wid] = q1; }
    __syncthreads();
    if (tid == 0) {
        float S0 = 0.f, Q0 = 0.f, S1 = 0.f, Q1 = 0.f;
        #pragma unroll
        for (int i = 0; i < 8; i++) {
            S0 += red[i]; Q0 += red[8 + i]; S1 += red[16 + i]; Q1 += red[24 + i];
        }
        int gbase = b * 4 + morph * 2;
        atomicAdd(&g_ssum[gbase], S0);     atomicAdd(&g_ssq[gbase], Q0);
        atomicAdd(&g_ssum[gbase + 1], S1); atomicAdd(&g_ssq[gbase + 1], Q1);
    }
}

// ---------------- GN+ReLU + concat + 1x1 conv (16->64) + BN + ReLU, packed ----------------
__global__ void __launch_bounds__(256) final_kernel(
        const float* __restrict__ gx_g, const float* __restrict__ gx_b,
        const float* __restrict__ gy_g, const float* __restrict__ gy_b,
        const float* __restrict__ w2,
        const float* __restrict__ bn2g, const float* __restrict__ bn2b,
        const float* __restrict__ bn2m, const float* __restrict__ bn2v,
        float* __restrict__ out) {
    __shared__ ull swt[16 * 32];         // [ch*32 + ocpair]
    __shared__ ull scp[32], shp[32];
    __shared__ float gnA[16], gnB[16];
    int tid = threadIdx.x;
    int idx = blockIdx.x * 256 + tid;
    int b = idx >> 16, p = idx & 65535;

    for (int i = tid; i < 512; i += 256) {
        int ch = i >> 5, op = i & 31;
        swt[i] = pk2(w2[(2 * op) * 16 + ch], w2[(2 * op + 1) * 16 + ch]);
    }
    if (tid < 32) {
        int oc0 = 2 * tid, oc1 = 2 * tid + 1;
        float sc0 = bn2g[oc0] * rsqrtf(bn2v[oc0] + EPSF);
        float sc1 = bn2g[oc1] * rsqrtf(bn2v[oc1] + EPSF);
        scp[tid] = pk2(sc0, sc1);
        shp[tid] = pk2(bn2b[oc0] - bn2m[oc0] * sc0, bn2b[oc1] - bn2m[oc1] * sc1);
    }
    if (tid < 16) {
        int ch = tid;
        int gi = b * 4 + ch / 4;
        float mean = g_ssum[gi] * (1.f / 262144.f);
        float var  = g_ssq[gi]  * (1.f / 262144.f) - mean * mean;
        float rs = rsqrtf(var + EPSF);
        float gamma = (ch < 8) ? gx_g[ch] : gy_g[ch - 8];
        float beta  = (ch < 8) ? gx_b[ch] : gy_b[ch - 8];
        gnA[ch] = rs * gamma; gnB[ch] = beta - mean * rs * gamma;
    }
    __syncthreads();

    ull catd[16];
    #pragma unroll
    for (int ch = 0; ch < 16; ch++) {
        float val = g_outraw[((size_t)b * 16 + ch) * HW1 + p];
        val = fmaxf(fmaf(val, gnA[ch], gnB[ch]), 0.f);
        catd[ch] = dup2(val);
    }

    ull acc[32];
    #pragma unroll
    for (int i = 0; i < 32; i++) acc[i] = 0ull;
    #pragma unroll
    for (int ch = 0; ch < 16; ch++) {
        const ulonglong2* wrow = (const ulonglong2*)(swt + ch * 32);
        #pragma unroll
        for (int op2 = 0; op2 < 16; op2++) {
            ulonglong2 ww = wrow[op2];
            fma2(acc[2 * op2], catd[ch], ww.x);
            fma2(acc[2 * op2 + 1], catd[ch], ww.y);
        }
    }

    float* obp = out + (size_t)b * 64 * HW1 + p;
    #pragma unroll
    for (int op = 0; op < 32; op++) {
        ull tmp = shp[op];
        fma2(tmp, acc[op], scp[op]);
        float2 vv = up2(tmp);
        obp[(size_t)(2 * op) * HW1]     = fmaxf(vv.x, 0.f);
        obp[(size_t)(2 * op + 1) * HW1] = fmaxf(vv.y, 0.f);
    }
}

// ---------------- launch ----------------
extern "C" void kernel_launch(void* const* d_in, const int* in_sizes, int n_in,
                              void* d_out, int out_size) {
    const float* x        = (const float*)d_in[0];
    const float* conv1_w  = (const float*)d_in[1];
    const float* bn1_g    = (const float*)d_in[2];
    const float* bn1_b    = (const float*)d_in[3];
    const float* bn1_m    = (const float*)d_in[4];
    const float* bn1_v    = (const float*)d_in[5];
    const float* offx_w   = (const float*)d_in[6];
    const float* offx_b   = (const float*)d_in[7];
    const float* gnoffx_g = (const float*)d_in[8];
    const float* gnoffx_b = (const float*)d_in[9];
    const float* dscx_w   = (const float*)d_in[10];
    const float* dscx_b   = (const float*)d_in[11];
    const float* gnx_g    = (const float*)d_in[12];
    const float* gnx_b    = (const float*)d_in[13];
    const float* offy_w   = (const float*)d_in[14];
    const float* offy_b   = (const float*)d_in[15];
    const float* gnoffy_g = (const float*)d_in[16];
    const float* gnoffy_b = (const float*)d_in[17];
    const float* dscy_w   = (const float*)d_in[18];
    const float* dscy_b   = (const float*)d_in[19];
    const float* gny_g    = (const float*)d_in[20];
    const float* gny_b    = (const float*)d_in[21];
    const float* conv2_w  = (const float*)d_in[22];
    const float* bn2_g    = (const float*)d_in[23];
    const float* bn2_b    = (const float*)d_in[24];
    const float* bn2_m    = (const float*)d_in[25];
    const float* bn2_v    = (const float*)d_in[26];
    float* out = (float*)d_out;

    zero_stats_kernel<<<1, 32>>>();
    conv1_kernel<<<512, 256>>>(x, conv1_w, bn1_g, bn1_b, bn1_m, bn1_v);
    offconv_kernel<<<dim3(16, 8, 2), dim3(16, 16)>>>(offx_w, offx_b, offy_w, offy_b);
    sample_kernel<<<dim3(512, 2), 256>>>(dscx_w, dscx_b, dscy_w, dscy_b,
                                         gnoffx_g, gnoffx_b, gnoffy_g, gnoffy_b);
    final_kernel<<<512, 256>>>(gnx_g, gnx_b, gny_g, gny_b, conv2_w,
                               bn2_g, bn2_b, bn2_m, bn2_v, out);
}

// round 3
// speedup vs baseline: 1.7181x; 1.2643x over previous
#include <cuda_runtime.h>
#include <math.h>

#define H1 256
#define W1 256
#define HW1 65536
#define EPSF 1e-5f

typedef unsigned long long ull;
typedef unsigned int u32;

__device__ __forceinline__ ull pk2(float a, float b) {
    ull r; asm("mov.b64 %0,{%1,%2};" : "=l"(r) : "f"(a), "f"(b)); return r;
}
__device__ __forceinline__ ull dup2(float a) {
    ull r; asm("mov.b64 %0,{%1,%1};" : "=l"(r) : "f"(a)); return r;
}
__device__ __forceinline__ void fma2(ull& d, ull a, ull b) {
    asm("fma.rn.f32x2 %0,%1,%2,%0;" : "+l"(d) : "l"(a), "l"(b));
}
__device__ __forceinline__ ull mul2(ull a, ull b) {
    ull r; asm("mul.rn.f32x2 %0,%1,%2;" : "=l"(r) : "l"(a), "l"(b)); return r;
}
__device__ __forceinline__ float2 up2(ull u) {
    float2 r; asm("mov.b64 {%0,%1},%2;" : "=f"(r.x), "=f"(r.y) : "l"(u)); return r;
}
__device__ __forceinline__ u32 s2u(const void* p) {
    u32 a; asm("{.reg .u64 t; cvta.to.shared.u64 t, %1; cvt.u32.u64 %0, t;}" : "=r"(a) : "l"(p));
    return a;
}
__device__ __forceinline__ void cp4(u32 dst, const void* src, int sz) {
    asm volatile("cp.async.ca.shared.global [%0], [%1], 4, %2;" :: "r"(dst), "l"(src), "r"(sz));
}
__device__ __forceinline__ void cp16(u32 dst, const void* src) {
    asm volatile("cp.async.cg.shared.global [%0], [%1], 16;" :: "r"(dst), "l"(src));
}
__device__ __forceinline__ void cp_commit() {
    asm volatile("cp.async.commit_group;");
}
template<int N> __device__ __forceinline__ void cp_wait() {
    asm volatile("cp.async.wait_group %0;" :: "n"(N));
}

// ---------------- scratch ----------------
__device__ float g_h[2 * 64 * HW1];
__device__ float g_off[2 * 8 * HW1];
__device__ float g_outraw[2 * 16 * HW1];
__device__ ull   g_woff[64 * 12 * 12];     // dup'd offconv weights [c][vch][12]
__device__ float g_osum[12], g_osq[12];    // b*6 + group
__device__ float g_ssum[8],  g_ssq[8];

// ---------------- prep: zero stats + build dup'd offconv weight table ----------------
__global__ void prep_kernel(const float* __restrict__ wx, const float* __restrict__ wy) {
    int idx = blockIdx.x * 256 + threadIdx.x;
    if (idx < 12) { g_osum[idx] = 0.f; g_osq[idx] = 0.f; }
    if (idx < 8)  { g_ssum[idx] = 0.f; g_ssq[idx] = 0.f; }
    if (idx < 9216) {
        int c = idx / 144, rem = idx - c * 144;
        int vch = rem / 12, t = rem - vch * 12;
        float val = 0.f;
        if (t < 9)
            val = (vch < 6) ? wx[vch * 576 + c * 9 + t]
                            : wy[(vch - 2) * 576 + c * 9 + t];
        g_woff[idx] = dup2(val);
    }
}

// ---------------- conv1 3x3 s2 pad1 (3->64) + BN + ReLU ----------------
__global__ void __launch_bounds__(256) conv1_kernel(
        const float* __restrict__ x, const float* __restrict__ w,
        const float* __restrict__ g, const float* __restrict__ bb,
        const float* __restrict__ m, const float* __restrict__ v) {
    __shared__ __align__(16) ull swp[864];
    __shared__ float ssc[64], ssh[64];
    int tid = threadIdx.x;
    for (int i = tid; i < 864; i += 256) {
        int t = i >> 5, op = i & 31;
        swp[i] = pk2(w[(2 * op) * 27 + t], w[(2 * op + 1) * 27 + t]);
    }
    if (tid < 64) {
        float sc = g[tid] * rsqrtf(v[tid] + EPSF);
        ssc[tid] = sc; ssh[tid] = bb[tid] - m[tid] * sc;
    }
    __syncthreads();

    int idx = blockIdx.x * 256 + tid;
    int b = idx >> 16, p = idx & 65535;
    int oy = p >> 8, ox = p & 255;
    const float* xb = x + (size_t)b * 3 * 512 * 512;

    ull pd[27];
    #pragma unroll
    for (int ic = 0; ic < 3; ic++)
        #pragma unroll
        for (int dy = 0; dy < 3; dy++) {
            int iy = 2 * oy - 1 + dy;
            #pragma unroll
            for (int dx = 0; dx < 3; dx++) {
                int ix = 2 * ox - 1 + dx;
                float val = 0.f;
                if (iy >= 0 && ix >= 0) val = xb[(ic * 512 + iy) * 512 + ix];
                pd[ic * 9 + dy * 3 + dx] = dup2(val);
            }
        }

    float* hb = g_h + (size_t)b * 64 * HW1 + p;
    #pragma unroll 1
    for (int half = 0; half < 2; half++) {
        ull acc[16];
        #pragma unroll
        for (int j = 0; j < 16; j++) acc[j] = 0ull;
        #pragma unroll
        for (int t = 0; t < 27; t++)
            #pragma unroll
            for (int j = 0; j < 16; j++)
                fma2(acc[j], pd[t], swp[t * 32 + half * 16 + j]);
        #pragma unroll
        for (int j = 0; j < 16; j++) {
            int oc = (half * 16 + j) * 2;
            float2 vv = up2(acc[j]);
            hb[(size_t)oc * HW1]       = fmaxf(fmaf(vv.x, ssc[oc],     ssh[oc]),     0.f);
            hb[(size_t)(oc + 1) * HW1] = fmaxf(fmaf(vv.y, ssc[oc + 1], ssh[oc + 1]), 0.f);
        }
    }
}

// ---------------- offset convs: 12 needed channels, cp.async pipelined ----------------
#define OTW 35
#define OTR 18
#define OTS (OTR * OTW)   // 630
__global__ void __launch_bounds__(256) offconv_kernel(
        const float* __restrict__ bxp, const float* __restrict__ byp) {
    __shared__ float st[2][2][OTS];
    __shared__ __align__(16) ull wsm[2][2][144];
    __shared__ float sbias[12];
    int tid = threadIdx.x, tx = tid & 31, tyy = tid >> 5;
    int b = blockIdx.z;
    int ox0 = blockIdx.x * 32, oy0 = blockIdx.y * 16;

    if (tid < 12) sbias[tid] = (tid < 6) ? bxp[tid] : byp[tid - 2];

    // fill-slot precompute (5 slots of 2*630)
    int fe[5], fsrc[5], fch[5], fsz[5];
    #pragma unroll
    for (int s = 0; s < 5; s++) {
        int i = tid + s * 256;
        int valid = (i < 1260);
        int ii = valid ? i : 0;
        int ch = (ii >= OTS) ? 1 : 0;
        int j = ii - ch * OTS;
        int r = j / OTW, cc = j - r * OTW;
        int gy = oy0 - 1 + r, gx = ox0 - 1 + cc;
        int ok = valid && gy >= 0 && gy < H1 && gx >= 0 && gx < W1 && cc < 34;
        fe[s] = ch * OTS + j;
        fch[s] = ch;
        fsrc[s] = min(max(gy, 0), 255) * W1 + min(max(gx, 0), 255);
        fsz[s] = ok ? 4 : 0;
        if (!valid) fsz[s] = -1;   // skip
    }
    u32 st0 = s2u(&st[0][0][0]), st1 = s2u(&st[1][0][0]);
    u32 ws0 = s2u(&wsm[0][0][0]), ws1 = s2u(&wsm[1][0][0]);
    const float* hb = g_h + (size_t)b * 64 * HW1;
    const char* wgp = (const char*)g_woff;

    __syncthreads();
    ull acc[12];
    #pragma unroll
    for (int i = 0; i < 12; i++) acc[i] = dup2(sbias[i]);

    // issue stage 0
    {
        #pragma unroll
        for (int s = 0; s < 5; s++)
            if (fsz[s] >= 0) cp4(st0 + fe[s] * 4, hb + (size_t)fch[s] * HW1 + fsrc[s], fsz[s]);
        if (tid < 144) {
            int chi = tid >= 72 ? 1 : 0, o = tid - chi * 72;
            cp16(ws0 + (chi * 144 + o * 2) * 8, wgp + ((size_t)chi * 72 + o) * 16);
        }
        cp_commit();
    }

    #pragma unroll 1
    for (int sg = 0; sg < 32; sg++) {
        int buf = sg & 1;
        if (sg + 1 < 32) {
            u32 std = buf ? st0 : st1;
            u32 wsd = buf ? ws0 : ws1;
            int cbase = 2 * (sg + 1);
            #pragma unroll
            for (int s = 0; s < 5; s++)
                if (fsz[s] >= 0) cp4(std + fe[s] * 4, hb + (size_t)(cbase + fch[s]) * HW1 + fsrc[s], fsz[s]);
            if (tid < 144) {
                int chi = tid >= 72 ? 1 : 0, o = tid - chi * 72;
                cp16(wsd + (chi * 144 + o * 2) * 8, wgp + ((size_t)(cbase + chi) * 72 + o) * 16);
            }
            cp_commit();
            cp_wait<1>();
        } else {
            cp_wait<0>();
        }
        __syncthreads();

        #pragma unroll
        for (int cc2 = 0; cc2 < 2; cc2++) {
            const float* tp = st[buf][cc2];
            ull pk[9];
            #pragma unroll
            for (int dy = 0; dy < 3; dy++)
                #pragma unroll
                for (int dx = 0; dx < 3; dx++)
                    pk[dy * 3 + dx] = pk2(tp[(tyy + dy) * OTW + tx + dx],
                                          tp[(tyy + 8 + dy) * OTW + tx + dx]);
            const ull* wc = wsm[buf][cc2];
            #pragma unroll
            for (int vch = 0; vch < 12; vch++) {
                const ulonglong2* wp = (const ulonglong2*)(wc + vch * 12);
                ulonglong2 w01 = wp[0], w23 = wp[1], w45 = wp[2], w67 = wp[3];
                ull w8 = wc[vch * 12 + 8];
                fma2(acc[vch], pk[0], w01.x); fma2(acc[vch], pk[1], w01.y);
                fma2(acc[vch], pk[2], w23.x); fma2(acc[vch], pk[3], w23.y);
                fma2(acc[vch], pk[4], w45.x); fma2(acc[vch], pk[5], w45.y);
                fma2(acc[vch], pk[6], w67.x); fma2(acc[vch], pk[7], w67.y);
                fma2(acc[vch], pk[8], w8);
            }
        }
        __syncthreads();
    }

    // stores: morph0 gets vch {0,1,3,4}, morph1 gets vch {7,8,10,11}
    int p0 = (oy0 + tyy) * W1 + ox0 + tx;
    int p1 = p0 + 8 * W1;
    const int chs[8] = {0, 1, 3, 4, 7, 8, 10, 11};
    float* ob = g_off + (size_t)b * 8 * HW1;
    #pragma unroll
    for (int s = 0; s < 8; s++) {
        float2 vv = up2(acc[chs[s]]);
        ob[(size_t)s * HW1 + p0] = vv.x;
        ob[(size_t)s * HW1 + p1] = vv.y;
    }

    // stats: 6 groups = vch pairs (0,1)(2,3)(4,5)(6,7)(8,9)(10,11)
    int lane = tid & 31;
    #pragma unroll
    for (int gi = 0; gi < 6; gi++) {
        float2 a = up2(acc[2 * gi]), c2 = up2(acc[2 * gi + 1]);
        float s = a.x + a.y + c2.x + c2.y;
        float q = a.x * a.x + a.y * a.y + c2.x * c2.x + c2.y * c2.y;
        #pragma unroll
        for (int o = 16; o > 0; o >>= 1) {
            s += __shfl_down_sync(0xffffffffu, s, o);
            q += __shfl_down_sync(0xffffffffu, q, o);
        }
        if (lane == 0) {
            atomicAdd(&g_osum[b * 6 + gi], s);
            atomicAdd(&g_osq[b * 6 + gi], q);
        }
    }
}

// ---------------- fused GN+tanh+cum + tiled bilinear sample + K-conv + stats ----------------
#define STW 38
#define STR 21
#define STS2 (STR * STW)   // 798
__global__ void __launch_bounds__(256) sample_kernel(
        const float* __restrict__ dwx, const float* __restrict__ dbx,
        const float* __restrict__ dwy, const float* __restrict__ dby,
        const float* __restrict__ gxg, const float* __restrict__ gxb,
        const float* __restrict__ gyg, const float* __restrict__ gyb) {
    int bz = blockIdx.z;
    int b = bz >> 1, morph = bz & 1;
    const float* dw = morph ? dwy : dwx;
    const float* db = morph ? dby : dbx;

    __shared__ float st[2][2][STS2];
    __shared__ __align__(16) ull sw[2560];
    __shared__ float sA[4], sB[4];
    int tid = threadIdx.x, tx = tid & 31, tyy = tid >> 5;
    int ox0 = blockIdx.x * 32, oy0 = blockIdx.y * 16;

    for (int i = tid; i < 2560; i += 256) sw[i] = dup2(dw[(i & 7) * 320 + (i >> 3)]);
    if (tid < 4) {
        int gi, ci; float gamma, beta;
        if (morph == 0) {
            const int gtab[4] = {0, 0, 1, 2}; const int ctab[4] = {0, 1, 3, 4};
            gi = b * 6 + gtab[tid]; ci = ctab[tid];
            gamma = gxg[ci]; beta = gxb[ci];
        } else {
            const int gtab[4] = {3, 4, 5, 5}; const int ctab[4] = {5, 6, 8, 9};
            gi = b * 6 + gtab[tid]; ci = ctab[tid];
            gamma = gyg[ci]; beta = gyb[ci];
        }
        float mean = g_osum[gi] * (1.f / 131072.f);
        float var  = g_osq[gi]  * (1.f / 131072.f) - mean * mean;
        float rs = rsqrtf(var + EPSF) * gamma;
        sA[tid] = rs; sB[tid] = beta - mean * rs;
    }

    // fill-slot precompute (7 slots of 2*798)
    int fe[7], fsrc[7], fch[7], fok[7];
    #pragma unroll
    for (int s = 0; s < 7; s++) {
        int i = tid + s * 256;
        int valid = (i < 1596);
        int ii = valid ? i : 0;
        int ch = (ii >= STS2) ? 1 : 0;
        int j = ii - ch * STS2;
        int r = j / STW, cc = j - r * STW;
        int gy = min(max(oy0 - 2 + r, 0), 255);
        int gx = min(max(ox0 - 2 + cc, 0), 255);
        fe[s] = ch * STS2 + j; fch[s] = ch;
        fsrc[s] = gy * W1 + gx;
        fok[s] = valid;
    }
    u32 st0 = s2u(&st[0][0][0]), st1 = s2u(&st[1][0][0]);
    const float* hb = g_h + (size_t)b * 64 * HW1;

    __syncthreads();

    // per-pixel taps (2 pixels: rows tyy and tyy+8)
    int ww = ox0 + tx;
    int o0[2][5], o1[2][5];
    float wtv[2][5];
    #pragma unroll
    for (int j = 0; j < 2; j++) {
        int hh = oy0 + tyy + 8 * j;
        int p = hh * W1 + ww;
        const float* ob = g_off + ((size_t)b * 8 + morph * 4) * HW1 + p;
        float t0 = tanhf(fmaf(ob[0 * (size_t)HW1], sA[0], sB[0]));
        float t1 = tanhf(fmaf(ob[1 * (size_t)HW1], sA[1], sB[1]));
        float t2 = tanhf(fmaf(ob[2 * (size_t)HW1], sA[2], sB[2]));
        float t3 = tanhf(fmaf(ob[3 * (size_t)HW1], sA[3], sB[3]));
        float cum[5] = {t0 + t1, t1, 0.f, t2, t2 + t3};
        #pragma unroll
        for (int k = 0; k < 5; k++) {
            if (morph == 0) {
                float y = fminf(fmaxf((float)hh + cum[k], 0.f), 255.f);
                float y0 = floorf(y);
                wtv[j][k] = y - y0;
                int i0 = (int)y0;
                int i1 = min(i0 + 1, 255);
                int xi = min(max(ww + k - 2, 0), 255);
                o0[j][k] = (i0 - oy0 + 2) * STW + (xi - ox0 + 2);
                o1[j][k] = (i1 - oy0 + 2) * STW + (xi - ox0 + 2);
            } else {
                float xx = fminf(fmaxf((float)ww + cum[k], 0.f), 255.f);
                float x0 = floorf(xx);
                wtv[j][k] = xx - x0;
                int i0 = (int)x0;
                int i1 = min(i0 + 1, 255);
                int yi = min(max(hh + k - 2, 0), 255);
                o0[j][k] = (yi - oy0 + 2) * STW + (i0 - ox0 + 2);
                o1[j][k] = (yi - oy0 + 2) * STW + (i1 - ox0 + 2);
            }
        }
    }
    ull wt2[5], om2[5];
    #pragma unroll
    for (int k = 0; k < 5; k++) {
        wt2[k] = pk2(wtv[0][k], wtv[1][k]);
        om2[k] = pk2(1.f - wtv[0][k], 1.f - wtv[1][k]);
    }

    ull acc[8];
    #pragma unroll
    for (int oc = 0; oc < 8; oc++) acc[oc] = dup2(db[oc]);

    // issue stage 0
    {
        #pragma unroll
        for (int s = 0; s < 7; s++)
            if (fok[s]) cp4(st0 + fe[s] * 4, hb + (size_t)fch[s] * HW1 + fsrc[s], 4);
        cp_commit();
    }

    #pragma unroll 1
    for (int sg = 0; sg < 32; sg++) {
        int buf = sg & 1;
        if (sg + 1 < 32) {
            u32 std = buf ? st0 : st1;
            int cbase = 2 * (sg + 1);
            #pragma unroll
            for (int s = 0; s < 7; s++)
                if (fok[s]) cp4(std + fe[s] * 4, hb + (size_t)(cbase + fch[s]) * HW1 + fsrc[s], 4);
            cp_commit();
            cp_wait<1>();
        } else {
            cp_wait<0>();
        }
        __syncthreads();

        #pragma unroll
        for (int cc2 = 0; cc2 < 2; cc2++) {
            int c = 2 * sg + cc2;
            const float* tp = st[buf][cc2];
            const ull* wb = sw + c * 40;
            #pragma unroll
            for (int k = 0; k < 5; k++) {
                float A0 = tp[o0[0][k]], A1 = tp[o0[1][k]];
                float B0 = tp[o1[0][k]], B1 = tp[o1[1][k]];
                ull a2 = pk2(A0, A1), b2 = pk2(B0, B1);
                ull v = mul2(om2[k], a2);
                fma2(v, wt2[k], b2);
                const ulonglong2* wp = (const ulonglong2*)(wb + k * 8);
                ulonglong2 w01 = wp[0], w23 = wp[1], w45 = wp[2], w67 = wp[3];
                fma2(acc[0], v, w01.x); fma2(acc[1], v, w01.y);
                fma2(acc[2], v, w23.x); fma2(acc[3], v, w23.y);
                fma2(acc[4], v, w45.x); fma2(acc[5], v, w45.y);
                fma2(acc[6], v, w67.x); fma2(acc[7], v, w67.y);
            }
        }
        __syncthreads();
    }

    int p0 = (oy0 + tyy) * W1 + ox0 + tx;
    int p1 = p0 + 8 * W1;
    float* op = g_outraw + ((size_t)b * 16 + morph * 8) * HW1;
    #pragma unroll
    for (int oc = 0; oc < 8; oc++) {
        float2 vv = up2(acc[oc]);
        op[(size_t)oc * HW1 + p0] = vv.x;
        op[(size_t)oc * HW1 + p1] = vv.y;
    }

    // stats: group0 = oc0-3, group1 = oc4-7
    int lane = tid & 31;
    #pragma unroll
    for (int gi = 0; gi < 2; gi++) {
        float s = 0.f, q = 0.f;
        #pragma unroll
        for (int oc = 4 * gi; oc < 4 * gi + 4; oc++) {
            float2 vv = up2(acc[oc]);
            s += vv.x + vv.y;
            q += vv.x * vv.x + vv.y * vv.y;
        }
        #pragma unroll
        for (int o = 16; o > 0; o >>= 1) {
            s += __shfl_down_sync(0xffffffffu, s, o);
            q += __shfl_down_sync(0xffffffffu, q, o);
        }
        if (lane == 0) {
            atomicAdd(&g_ssum[b * 4 + morph * 2 + gi], s);
            atomicAdd(&g_ssq[b * 4 + morph * 2 + gi], q);
        }
    }
}

// ---------------- GN+ReLU + concat + 1x1 conv (16->64) + BN + ReLU ----------------
__global__ void __launch_bounds__(256) final_kernel(
        const float* __restrict__ gx_g, const float* __restrict__ gx_b,
        const float* __restrict__ gy_g, const float* __restrict__ gy_b,
        const float* __restrict__ w2,
        const float* __restrict__ bn2g, const float* __restrict__ bn2b,
        const float* __restrict__ bn2m, const float* __restrict__ bn2v,
        float* __restrict__ out) {
    __shared__ __align__(16) ull swt[16 * 32];
    __shared__ ull scp[32], shp[32];
    __shared__ float gnA[16], gnB[16];
    int tid = threadIdx.x;
    int idx = blockIdx.x * 256 + tid;
    int b = idx >> 16, p = idx & 65535;

    for (int i = tid; i < 512; i += 256) {
        int ch = i >> 5, op = i & 31;
        swt[i] = pk2(w2[(2 * op) * 16 + ch], w2[(2 * op + 1) * 16 + ch]);
    }
    if (tid < 32) {
        int oc0 = 2 * tid, oc1 = 2 * tid + 1;
        float sc0 = bn2g[oc0] * rsqrtf(bn2v[oc0] + EPSF);
        float sc1 = bn2g[oc1] * rsqrtf(bn2v[oc1] + EPSF);
        scp[tid] = pk2(sc0, sc1);
        shp[tid] = pk2(bn2b[oc0] - bn2m[oc0] * sc0, bn2b[oc1] - bn2m[oc1] * sc1);
    }
    if (tid < 16) {
        int ch = tid;
        int gi = b * 4 + ch / 4;
        float mean = g_ssum[gi] * (1.f / 262144.f);
        float var  = g_ssq[gi]  * (1.f / 262144.f) - mean * mean;
        float rs = rsqrtf(var + EPSF);
        float gamma = (ch < 8) ? gx_g[ch] : gy_g[ch - 8];
        float beta  = (ch < 8) ? gx_b[ch] : gy_b[ch - 8];
        gnA[ch] = rs * gamma; gnB[ch] = beta - mean * rs * gamma;
    }
    __syncthreads();

    ull catd[16];
    #pragma unroll
    for (int ch = 0; ch < 16; ch++) {
        float val = g_outraw[((size_t)b * 16 + ch) * HW1 + p];
        val = fmaxf(fmaf(val, gnA[ch], gnB[ch]), 0.f);
        catd[ch] = dup2(val);
    }

    ull acc[32];
    #pragma unroll
    for (int i = 0; i < 32; i++) acc[i] = 0ull;
    #pragma unroll
    for (int ch = 0; ch < 16; ch++) {
        const ulonglong2* wrow = (const ulonglong2*)(swt + ch * 32);
        #pragma unroll
        for (int op2 = 0; op2 < 16; op2++) {
            ulonglong2 ww = wrow[op2];
            fma2(acc[2 * op2], catd[ch], ww.x);
            fma2(acc[2 * op2 + 1], catd[ch], ww.y);
        }
    }

    float* obp = out + (size_t)b * 64 * HW1 + p;
    #pragma unroll
    for (int op = 0; op < 32; op++) {
        ull tmp = shp[op];
        fma2(tmp, acc[op], scp[op]);
        float2 vv = up2(tmp);
        obp[(size_t)(2 * op) * HW1]     = fmaxf(vv.x, 0.f);
        obp[(size_t)(2 * op + 1) * HW1] = fmaxf(vv.y, 0.f);
    }
}

// ---------------- launch ----------------
extern "C" void kernel_launch(void* const* d_in, const int* in_sizes, int n_in,
                              void* d_out, int out_size) {
    const float* x        = (const float*)d_in[0];
    const float* conv1_w  = (const float*)d_in[1];
    const float* bn1_g    = (const float*)d_in[2];
    const float* bn1_b    = (const float*)d_in[3];
    const float* bn1_m    = (const float*)d_in[4];
    const float* bn1_v    = (const float*)d_in[5];
    const float* offx_w   = (const float*)d_in[6];
    const float* offx_b   = (const float*)d_in[7];
    const float* gnoffx_g = (const float*)d_in[8];
    const float* gnoffx_b = (const float*)d_in[9];
    const float* dscx_w   = (const float*)d_in[10];
    const float* dscx_b   = (const float*)d_in[11];
    const float* gnx_g    = (const float*)d_in[12];
    const float* gnx_b    = (const float*)d_in[13];
    const float* offy_w   = (const float*)d_in[14];
    const float* offy_b   = (const float*)d_in[15];
    const float* gnoffy_g = (const float*)d_in[16];
    const float* gnoffy_b = (const float*)d_in[17];
    const float* dscy_w   = (const float*)d_in[18];
    const float* dscy_b   = (const float*)d_in[19];
    const float* gny_g    = (const float*)d_in[20];
    const float* gny_b    = (const float*)d_in[21];
    const float* conv2_w  = (const float*)d_in[22];
    const float* bn2_g    = (const float*)d_in[23];
    const float* bn2_b    = (const float*)d_in[24];
    const float* bn2_m    = (const float*)d_in[25];
    const float* bn2_v    = (const float*)d_in[26];
    float* out = (float*)d_out;

    prep_kernel<<<36, 256>>>(offx_w, offy_w);
    conv1_kernel<<<512, 256>>>(x, conv1_w, bn1_g, bn1_b, bn1_m, bn1_v);
    offconv_kernel<<<dim3(8, 16, 2), 256>>>(offx_b, offy_b);
    sample_kernel<<<dim3(8, 16, 4), 256>>>(dscx_w, dscx_b, dscy_w, dscy_b,
                                           gnoffx_g, gnoffx_b, gnoffy_g, gnoffy_b);
    final_kernel<<<512, 256>>>(gnx_g, gnx_b, gny_g, gny_b, conv2_w,
                               bn2_g, bn2_b, bn2_m, bn2_v, out);
}

// round 5
// speedup vs baseline: 1.8833x; 1.0961x over previous
#include <cuda_runtime.h>
#include <math.h>

#define H1 256
#define W1 256
#define HW1 65536
#define EPSF 1e-5f

typedef unsigned long long ull;
typedef unsigned int u32;

__device__ __forceinline__ ull pk2(float a, float b) {
    ull r; asm("mov.b64 %0,{%1,%2};" : "=l"(r) : "f"(a), "f"(b)); return r;
}
__device__ __forceinline__ ull dup2(float a) {
    ull r; asm("mov.b64 %0,{%1,%1};" : "=l"(r) : "f"(a)); return r;
}
__device__ __forceinline__ void fma2(ull& d, ull a, ull b) {
    asm("fma.rn.f32x2 %0,%1,%2,%0;" : "+l"(d) : "l"(a), "l"(b));
}
__device__ __forceinline__ float2 up2(ull u) {
    float2 r; asm("mov.b64 {%0,%1},%2;" : "=f"(r.x), "=f"(r.y) : "l"(u)); return r;
}
__device__ __forceinline__ u32 s2u(const void* p) {
    u32 a; asm("{.reg .u64 t; cvta.to.shared.u64 t, %1; cvt.u32.u64 %0, t;}" : "=r"(a) : "l"(p));
    return a;
}
__device__ __forceinline__ void cp4(u32 dst, const void* src, int sz) {
    asm volatile("cp.async.ca.shared.global [%0], [%1], 4, %2;" :: "r"(dst), "l"(src), "r"(sz));
}
__device__ __forceinline__ void cp16(u32 dst, const void* src) {
    asm volatile("cp.async.cg.shared.global [%0], [%1], 16;" :: "r"(dst), "l"(src));
}
__device__ __forceinline__ void cp_commit() {
    asm volatile("cp.async.commit_group;");
}
template<int N> __device__ __forceinline__ void cp_wait() {
    asm volatile("cp.async.wait_group %0;" :: "n"(N));
}

// ---------------- scratch ----------------
__device__ float g_h[2 * 64 * HW1 + 256];   // +256 zero pad for o0+stride overreads
__device__ float g_off[2 * 8 * HW1];
__device__ float g_outraw[2 * 16 * HW1];
__device__ ull   g_woff[64 * 12 * 12];      // dup'd offconv weights [c][vch][12]
__device__ float g_osum[12], g_osq[12];     // b*6 + group
__device__ float g_ssum[8],  g_ssq[8];

// ---------------- prep: zero stats + pad + build dup'd offconv weight table ----------------
__global__ void prep_kernel(const float* __restrict__ wx, const float* __restrict__ wy) {
    int idx = blockIdx.x * 256 + threadIdx.x;
    if (idx < 12) { g_osum[idx] = 0.f; g_osq[idx] = 0.f; }
    if (idx < 8)  { g_ssum[idx] = 0.f; g_ssq[idx] = 0.f; }
    if (idx < 256) g_h[2 * 64 * HW1 + idx] = 0.f;
    if (idx < 9216) {
        int c = idx / 144, rem = idx - c * 144;
        int vch = rem / 12, t = rem - vch * 12;
        float val = 0.f;
        if (t < 9)
            val = (vch < 6) ? wx[vch * 576 + c * 9 + t]
                            : wy[(vch - 2) * 576 + c * 9 + t];
        g_woff[idx] = dup2(val);
    }
}

// ---------------- conv1 3x3 s2 pad1 (3->64) + BN + ReLU ----------------
__global__ void __launch_bounds__(256) conv1_kernel(
        const float* __restrict__ x, const float* __restrict__ w,
        const float* __restrict__ g, const float* __restrict__ bb,
        const float* __restrict__ m, const float* __restrict__ v) {
    __shared__ __align__(16) ull swp[864];
    __shared__ float ssc[64], ssh[64];
    int tid = threadIdx.x;
    for (int i = tid; i < 864; i += 256) {
        int t = i >> 5, op = i & 31;
        swp[i] = pk2(w[(2 * op) * 27 + t], w[(2 * op + 1) * 27 + t]);
    }
    if (tid < 64) {
        float sc = g[tid] * rsqrtf(v[tid] + EPSF);
        ssc[tid] = sc; ssh[tid] = bb[tid] - m[tid] * sc;
    }
    __syncthreads();

    int idx = blockIdx.x * 256 + tid;
    int b = idx >> 16, p = idx & 65535;
    int oy = p >> 8, ox = p & 255;
    const float* xb = x + (size_t)b * 3 * 512 * 512;

    ull pd[27];
    #pragma unroll
    for (int ic = 0; ic < 3; ic++)
        #pragma unroll
        for (int dy = 0; dy < 3; dy++) {
            int iy = 2 * oy - 1 + dy;
            #pragma unroll
            for (int dx = 0; dx < 3; dx++) {
                int ix = 2 * ox - 1 + dx;
                float val = 0.f;
                if (iy >= 0 && ix >= 0) val = xb[(ic * 512 + iy) * 512 + ix];
                pd[ic * 9 + dy * 3 + dx] = dup2(val);
            }
        }

    float* hb = g_h + (size_t)b * 64 * HW1 + p;
    #pragma unroll 1
    for (int half = 0; half < 2; half++) {
        ull acc[16];
        #pragma unroll
        for (int j = 0; j < 16; j++) acc[j] = 0ull;
        #pragma unroll
        for (int t = 0; t < 27; t++)
            #pragma unroll
            for (int j = 0; j < 16; j++)
                fma2(acc[j], pd[t], swp[t * 32 + half * 16 + j]);
        #pragma unroll
        for (int j = 0; j < 16; j++) {
            int oc = (half * 16 + j) * 2;
            float2 vv = up2(acc[j]);
            hb[(size_t)oc * HW1]       = fmaxf(fmaf(vv.x, ssc[oc],     ssh[oc]),     0.f);
            hb[(size_t)(oc + 1) * HW1] = fmaxf(fmaf(vv.y, ssc[oc + 1], ssh[oc + 1]), 0.f);
        }
    }
}

// ---------------- offset convs: 12 needed channels, cp.async pipelined ----------------
#define OTW 35
#define OTR 18
#define OTS (OTR * OTW)   // 630
__global__ void __launch_bounds__(256) offconv_kernel(
        const float* __restrict__ bxp, const float* __restrict__ byp) {
    __shared__ float st[2][2][OTS];
    __shared__ __align__(16) ull wsm[2][2][144];
    __shared__ float sbias[12];
    int tid = threadIdx.x, tx = tid & 31, tyy = tid >> 5;
    int b = blockIdx.z;
    int ox0 = blockIdx.x * 32, oy0 = blockIdx.y * 16;

    if (tid < 12) sbias[tid] = (tid < 6) ? bxp[tid] : byp[tid - 2];

    int fe[5], fsrc[5], fch[5], fsz[5];
    #pragma unroll
    for (int s = 0; s < 5; s++) {
        int i = tid + s * 256;
        int valid = (i < 1260);
        int ii = valid ? i : 0;
        int ch = (ii >= OTS) ? 1 : 0;
        int j = ii - ch * OTS;
        int r = j / OTW, cc = j - r * OTW;
        int gy = oy0 - 1 + r, gx = ox0 - 1 + cc;
        int ok = valid && gy >= 0 && gy < H1 && gx >= 0 && gx < W1 && cc < 34;
        fe[s] = ch * OTS + j;
        fch[s] = ch;
        fsrc[s] = min(max(gy, 0), 255) * W1 + min(max(gx, 0), 255);
        fsz[s] = ok ? 4 : 0;
        if (!valid) fsz[s] = -1;
    }
    u32 st0 = s2u(&st[0][0][0]), st1 = s2u(&st[1][0][0]);
    u32 ws0 = s2u(&wsm[0][0][0]), ws1 = s2u(&wsm[1][0][0]);
    const float* hb = g_h + (size_t)b * 64 * HW1;
    const char* wgp = (const char*)g_woff;

    __syncthreads();
    ull acc[12];
    #pragma unroll
    for (int i = 0; i < 12; i++) acc[i] = dup2(sbias[i]);

    {
        #pragma unroll
        for (int s = 0; s < 5; s++)
            if (fsz[s] >= 0) cp4(st0 + fe[s] * 4, hb + (size_t)fch[s] * HW1 + fsrc[s], fsz[s]);
        if (tid < 144) {
            int chi = tid >= 72 ? 1 : 0, o = tid - chi * 72;
            cp16(ws0 + (chi * 144 + o * 2) * 8, wgp + ((size_t)chi * 72 + o) * 16);
        }
        cp_commit();
    }

    #pragma unroll 1
    for (int sg = 0; sg < 32; sg++) {
        int buf = sg & 1;
        if (sg + 1 < 32) {
            u32 std = buf ? st0 : st1;
            u32 wsd = buf ? ws0 : ws1;
            int cbase = 2 * (sg + 1);
            #pragma unroll
            for (int s = 0; s < 5; s++)
                if (fsz[s] >= 0) cp4(std + fe[s] * 4, hb + (size_t)(cbase + fch[s]) * HW1 + fsrc[s], fsz[s]);
            if (tid < 144) {
                int chi = tid >= 72 ? 1 : 0, o = tid - chi * 72;
                cp16(wsd + (chi * 144 + o * 2) * 8, wgp + ((size_t)(cbase + chi) * 72 + o) * 16);
            }
            cp_commit();
            cp_wait<1>();
        } else {
            cp_wait<0>();
        }
        __syncthreads();

        #pragma unroll
        for (int cc2 = 0; cc2 < 2; cc2++) {
            const float* tp = st[buf][cc2];
            ull pk[9];
            #pragma unroll
            for (int dy = 0; dy < 3; dy++)
                #pragma unroll
                for (int dx = 0; dx < 3; dx++)
                    pk[dy * 3 + dx] = pk2(tp[(tyy + dy) * OTW + tx + dx],
                                          tp[(tyy + 8 + dy) * OTW + tx + dx]);
            const ull* wc = wsm[buf][cc2];
            #pragma unroll
            for (int vch = 0; vch < 12; vch++) {
                const ulonglong2* wp = (const ulonglong2*)(wc + vch * 12);
                ulonglong2 w01 = wp[0], w23 = wp[1], w45 = wp[2], w67 = wp[3];
                ull w8 = wc[vch * 12 + 8];
                fma2(acc[vch], pk[0], w01.x); fma2(acc[vch], pk[1], w01.y);
                fma2(acc[vch], pk[2], w23.x); fma2(acc[vch], pk[3], w23.y);
                fma2(acc[vch], pk[4], w45.x); fma2(acc[vch], pk[5], w45.y);
                fma2(acc[vch], pk[6], w67.x); fma2(acc[vch], pk[7], w67.y);
                fma2(acc[vch], pk[8], w8);
            }
        }
        __syncthreads();
    }

    int p0 = (oy0 + tyy) * W1 + ox0 + tx;
    int p1 = p0 + 8 * W1;
    const int chs[8] = {0, 1, 3, 4, 7, 8, 10, 11};
    float* ob = g_off + (size_t)b * 8 * HW1;
    #pragma unroll
    for (int s = 0; s < 8; s++) {
        float2 vv = up2(acc[chs[s]]);
        ob[(size_t)s * HW1 + p0] = vv.x;
        ob[(size_t)s * HW1 + p1] = vv.y;
    }

    int lane = tid & 31;
    #pragma unroll
    for (int gi = 0; gi < 6; gi++) {
        float2 a = up2(acc[2 * gi]), c2 = up2(acc[2 * gi + 1]);
        float s = a.x + a.y + c2.x + c2.y;
        float q = a.x * a.x + a.y * a.y + c2.x * c2.x + c2.y * c2.y;
        #pragma unroll
        for (int o = 16; o > 0; o >>= 1) {
            s += __shfl_down_sync(0xffffffffu, s, o);
            q += __shfl_down_sync(0xffffffffu, q, o);
        }
        if (lane == 0) {
            atomicAdd(&g_osum[b * 6 + gi], s);
            atomicAdd(&g_osq[b * 6 + gi], q);
        }
    }
}

// ---------------- fused GN+tanh+cum + direct-gather sample + K-conv + stats ----------------
// 2 px/thread (rows y and y+128); second tap = first + stride (wt=0 at clamp, pad covers OOB)
__global__ void __launch_bounds__(256) sample_kernel(
        const float* __restrict__ dwx, const float* __restrict__ dbx,
        const float* __restrict__ dwy, const float* __restrict__ dby,
        const float* __restrict__ gxg, const float* __restrict__ gxb,
        const float* __restrict__ gyg, const float* __restrict__ gyb) {
    int bz = blockIdx.y;
    int b = bz >> 1, morph = bz & 1;
    const float* dw = morph ? dwy : dwx;
    const float* db = morph ? dby : dbx;

    __shared__ __align__(16) ull sw[1280];   // [(c*5+k)*4 + ocp] = (w[2ocp], w[2ocp+1])
    __shared__ float sA[4], sB[4];
    int tid = threadIdx.x;
    for (int i = tid; i < 1280; i += 256) {
        int ocp = i & 3, ck = i >> 2;
        sw[i] = pk2(dw[(2 * ocp) * 320 + ck], dw[(2 * ocp + 1) * 320 + ck]);
    }
    if (tid < 4) {
        int gi, ci; float gamma, beta;
        if (morph == 0) {
            const int gtab[4] = {0, 0, 1, 2}; const int ctab[4] = {0, 1, 3, 4};
            gi = b * 6 + gtab[tid]; ci = ctab[tid];
            gamma = gxg[ci]; beta = gxb[ci];
        } else {
            const int gtab[4] = {3, 4, 5, 5}; const int ctab[4] = {5, 6, 8, 9};
            gi = b * 6 + gtab[tid]; ci = ctab[tid];
            gamma = gyg[ci]; beta = gyb[ci];
        }
        float mean = g_osum[gi] * (1.f / 131072.f);
        float var  = g_osq[gi]  * (1.f / 131072.f) - mean * mean;
        float rs = rsqrtf(var + EPSF) * gamma;
        sA[tid] = rs; sB[tid] = beta - mean * rs;
    }
    __syncthreads();

    int pix = blockIdx.x * 256 + tid;        // 0..32767
    int hh = pix >> 8, ww = pix & 255;
    int stride = morph ? 1 : W1;

    int o0[2][5];
    float wt[2][5];
    #pragma unroll
    for (int j = 0; j < 2; j++) {
        int yy = hh + 128 * j;
        int p = yy * W1 + ww;
        const float* ob = g_off + ((size_t)b * 8 + morph * 4) * HW1 + p;
        float t0 = tanhf(fmaf(ob[0 * (size_t)HW1], sA[0], sB[0]));
        float t1 = tanhf(fmaf(ob[1 * (size_t)HW1], sA[1], sB[1]));
        float t2 = tanhf(fmaf(ob[2 * (size_t)HW1], sA[2], sB[2]));
        float t3 = tanhf(fmaf(ob[3 * (size_t)HW1], sA[3], sB[3]));
        float cum[5] = {t0 + t1, t1, 0.f, t2, t2 + t3};
        #pragma unroll
        for (int k = 0; k < 5; k++) {
            if (morph == 0) {
                float y = fminf(fmaxf((float)yy + cum[k], 0.f), 255.f);
                float y0 = floorf(y);
                wt[j][k] = y - y0;
                int xi = min(max(ww + k - 2, 0), 255);
                o0[j][k] = (int)y0 * W1 + xi;
            } else {
                float xx = fminf(fmaxf((float)ww + cum[k], 0.f), 255.f);
                float x0 = floorf(xx);
                wt[j][k] = xx - x0;
                int yi = min(max(yy + k - 2, 0), 255);
                o0[j][k] = yi * W1 + (int)x0;
            }
        }
    }

    ull acc[2][4];
    #pragma unroll
    for (int j = 0; j < 2; j++)
        #pragma unroll
        for (int ocp = 0; ocp < 4; ocp++)
            acc[j][ocp] = pk2(db[2 * ocp], db[2 * ocp + 1]);

    const float* hb = g_h + (size_t)b * 64 * HW1;
    #pragma unroll 1
    for (int c = 0; c < 64; c++) {
        const float* hp = hb + (size_t)c * HW1;
        const ulonglong2* wp = (const ulonglong2*)(sw + c * 20);
        #pragma unroll
        for (int k = 0; k < 5; k++) {
            ulonglong2 wA = wp[k * 2];
            ulonglong2 wB = wp[k * 2 + 1];
            #pragma unroll
            for (int j = 0; j < 2; j++) {
                float a = hp[o0[j][k]];
                float v;
                if (k == 2) {
                    v = a;
                } else {
                    float b2 = hp[o0[j][k] + stride];
                    v = fmaf(wt[j][k], b2 - a, a);
                }
                ull v2 = dup2(v);
                fma2(acc[j][0], v2, wA.x); fma2(acc[j][1], v2, wA.y);
                fma2(acc[j][2], v2, wB.x); fma2(acc[j][3], v2, wB.y);
            }
        }
    }

    float* op = g_outraw + ((size_t)b * 16 + morph * 8) * HW1;
    #pragma unroll
    for (int j = 0; j < 2; j++) {
        int p = (hh + 128 * j) * W1 + ww;
        #pragma unroll
        for (int ocp = 0; ocp < 4; ocp++) {
            float2 vv = up2(acc[j][ocp]);
            op[(size_t)(2 * ocp) * HW1 + p]     = vv.x;
            op[(size_t)(2 * ocp + 1) * HW1 + p] = vv.y;
        }
    }

    // stats: group0 = oc0-3 (acc[*][0..1]), group1 = oc4-7 (acc[*][2..3])
    int lane = tid & 31;
    #pragma unroll
    for (int gi = 0; gi < 2; gi++) {
        float s = 0.f, q = 0.f;
        #pragma unroll
        for (int j = 0; j < 2; j++)
            #pragma unroll
            for (int ocp = 2 * gi; ocp < 2 * gi + 2; ocp++) {
                float2 vv = up2(acc[j][ocp]);
                s += vv.x + vv.y;
                q += vv.x * vv.x + vv.y * vv.y;
            }
        #pragma unroll
        for (int o = 16; o > 0; o >>= 1) {
            s += __shfl_down_sync(0xffffffffu, s, o);
            q += __shfl_down_sync(0xffffffffu, q, o);
        }
        if (lane == 0) {
            atomicAdd(&g_ssum[b * 4 + morph * 2 + gi], s);
            atomicAdd(&g_ssq[b * 4 + morph * 2 + gi], q);
        }
    }
}

// ---------------- GN+ReLU + concat + 1x1 conv (16->64) + BN + ReLU ----------------
__global__ void __launch_bounds__(256) final_kernel(
        const float* __restrict__ gx_g, const float* __restrict__ gx_b,
        const float* __restrict__ gy_g, const float* __restrict__ gy_b,
        const float* __restrict__ w2,
        const float* __restrict__ bn2g, const float* __restrict__ bn2b,
        const float* __restrict__ bn2m, const float* __restrict__ bn2v,
        float* __restrict__ out) {
    __shared__ __align__(16) ull swt[16 * 32];
    __shared__ ull scp[32], shp[32];
    __shared__ float gnA[16], gnB[16];
    int tid = threadIdx.x;
    int idx = blockIdx.x * 256 + tid;
    int b = idx >> 16, p = idx & 65535;

    for (int i = tid; i < 512; i += 256) {
        int ch = i >> 5, op = i & 31;
        swt[i] = pk2(w2[(2 * op) * 16 + ch], w2[(2 * op + 1) * 16 + ch]);
    }
    if (tid < 32) {
        int oc0 = 2 * tid, oc1 = 2 * tid + 1;
        float sc0 = bn2g[oc0] * rsqrtf(bn2v[oc0] + EPSF);
        float sc1 = bn2g[oc1] * rsqrtf(bn2v[oc1] + EPSF);
        scp[tid] = pk2(sc0, sc1);
        shp[tid] = pk2(bn2b[oc0] - bn2m[oc0] * sc0, bn2b[oc1] - bn2m[oc1] * sc1);
    }
    if (tid < 16) {
        int ch = tid;
        int gi = b * 4 + ch / 4;
        float mean = g_ssum[gi] * (1.f / 262144.f);
        float var  = g_ssq[gi]  * (1.f / 262144.f) - mean * mean;
        float rs = rsqrtf(var + EPSF);
        float gamma = (ch < 8) ? gx_g[ch] : gy_g[ch - 8];
        float beta  = (ch < 8) ? gx_b[ch] : gy_b[ch - 8];
        gnA[ch] = rs * gamma; gnB[ch] = beta - mean * rs * gamma;
    }
    __syncthreads();

    ull catd[16];
    #pragma unroll
    for (int ch = 0; ch < 16; ch++) {
        float val = g_outraw[((size_t)b * 16 + ch) * HW1 + p];
        val = fmaxf(fmaf(val, gnA[ch], gnB[ch]), 0.f);
        catd[ch] = dup2(val);
    }

    ull acc[32];
    #pragma unroll
    for (int i = 0; i < 32; i++) acc[i] = 0ull;
    #pragma unroll
    for (int ch = 0; ch < 16; ch++) {
        const ulonglong2* wrow = (const ulonglong2*)(swt + ch * 32);
        #pragma unroll
        for (int op2 = 0; op2 < 16; op2++) {
            ulonglong2 ww = wrow[op2];
            fma2(acc[2 * op2], catd[ch], ww.x);
            fma2(acc[2 * op2 + 1], catd[ch], ww.y);
        }
    }

    float* obp = out + (size_t)b * 64 * HW1 + p;
    #pragma unroll
    for (int op = 0; op < 32; op++) {
        ull tmp = shp[op];
        fma2(tmp, acc[op], scp[op]);
        float2 vv = up2(tmp);
        obp[(size_t)(2 * op) * HW1]     = fmaxf(vv.x, 0.f);
        obp[(size_t)(2 * op + 1) * HW1] = fmaxf(vv.y, 0.f);
    }
}

// ---------------- launch ----------------
extern "C" void kernel_launch(void* const* d_in, const int* in_sizes, int n_in,
                              void* d_out, int out_size) {
    const float* x        = (const float*)d_in[0];
    const float* conv1_w  = (const float*)d_in[1];
    const float* bn1_g    = (const float*)d_in[2];
    const float* bn1_b    = (const float*)d_in[3];
    const float* bn1_m    = (const float*)d_in[4];
    const float* bn1_v    = (const float*)d_in[5];
    const float* offx_w   = (const float*)d_in[6];
    const float* offx_b   = (const float*)d_in[7];
    const float* gnoffx_g = (const float*)d_in[8];
    const float* gnoffx_b = (const float*)d_in[9];
    const float* dscx_w   = (const float*)d_in[10];
    const float* dscx_b   = (const float*)d_in[11];
    const float* gnx_g    = (const float*)d_in[12];
    const float* gnx_b    = (const float*)d_in[13];
    const float* offy_w   = (const float*)d_in[14];
    const float* offy_b   = (const float*)d_in[15];
    const float* gnoffy_g = (const float*)d_in[16];
    const float* gnoffy_b = (const float*)d_in[17];
    const float* dscy_w   = (const float*)d_in[18];
    const float* dscy_b   = (const float*)d_in[19];
    const float* gny_g    = (const float*)d_in[20];
    const float* gny_b    = (const float*)d_in[21];
    const float* conv2_w  = (const float*)d_in[22];
    const float* bn2_g    = (const float*)d_in[23];
    const float* bn2_b    = (const float*)d_in[24];
    const float* bn2_m    = (const float*)d_in[25];
    const float* bn2_v    = (const float*)d_in[26];
    float* out = (float*)d_out;

    prep_kernel<<<36, 256>>>(offx_w, offy_w);
    conv1_kernel<<<512, 256>>>(x, conv1_w, bn1_g, bn1_b, bn1_m, bn1_v);
    offconv_kernel<<<dim3(8, 16, 2), 256>>>(offx_b, offy_b);
    sample_kernel<<<dim3(128, 4), 256>>>(dscx_w, dscx_b, dscy_w, dscy_b,
                                         gnoffx_g, gnoffx_b, gnoffy_g, gnoffy_b);
    final_kernel<<<512, 256>>>(gnx_g, gnx_b, gny_g, gny_b, conv2_w,
                               bn2_g, bn2_b, bn2_m, bn2_v, out);
}